// round 10
// baseline (speedup 1.0000x reference)
#include <cuda_runtime.h>
#include <math.h>
#include <stdint.h>

// Problem dims
#define TT   512
#define DD   256
#define HH   256
#define H2   512

#define NCHUNK 16
#define LCH    32

// smem layout (floats)
#define STRA 260                       // padded k-major row stride (16B-aligned rows)
#define AS_OFF 0                       // as[32][260]
#define BS_OFF (32 * STRA)             // bs[64][260]
#define P0_OFF (BS_OFF + 64 * STRA)    // P0[32][68] (k-half 0 partials)
#define P1_OFF (P0_OFF + 32 * 68)      // P1[32][68] (k-half 1 partials)
#define SS_STR 68
#define ES_OFF AS_OFF                  // Es[8][64] reuses as[] after GEMM
#define EP_OFF (P1_OFF + 32 * 68)      // epoch broadcast (1 int)
#define SMEM_FLOATS (EP_OFF + 1)
#define SMEM_BYTES (SMEM_FLOATS * 4)   // ~117 KB -> 1 block/SM

#define FLAG_STRIDE 32                 // 128 B between chunk flags

__device__ float g_E[NCHUNK * H2];     // per-chunk end states
__device__ int   g_flag[NCHUNK * FLAG_STRIDE];  // monotonic publish counters

#define FMA2(acc, a, b) \
    asm("fma.rn.f32x2 %0, %1, %2, %0;" : "+l"(acc) : "l"(a), "l"(b))

__device__ __forceinline__ float f32x2_sum(unsigned long long v) {
    float lo, hi;
    asm("mov.b64 {%0, %1}, %2;" : "=f"(lo), "=f"(hi) : "l"(v));
    return lo + hi;
}

__device__ __forceinline__ void cp16(float* smem_dst, const void* gsrc) {
    uint32_t sa = (uint32_t)__cvta_generic_to_shared(smem_dst);
    asm volatile("cp.async.cg.shared.global [%0], [%1], 16;" :: "r"(sa), "l"(gsrc));
}
#define CP_COMMIT() asm volatile("cp.async.commit_group;" ::: "memory")
#define CP_WAIT(n)  asm volatile("cp.async.wait_group %0;" :: "n"(n) : "memory")

__device__ __forceinline__ void cmul(float a, float b, float& p1, float& p2) {
    float n1 = a * p1 - b * p2;
    float n2 = fmaf(a, p2, b * p1);
    p1 = n1; p2 = n2;
}

__device__ __forceinline__ void coeffs(const float* __restrict__ lamda,
                                       const float* __restrict__ theta,
                                       int h, float& c, float& s, float& gam)
{
    float e = expf(lamda[h]);
    float y = expf(-e);
    float z = expf(theta[h]);
    gam = sqrtf(fmaxf(1.0f - y * y, 0.0f));
    float cz, sz;
    sincosf(z, &sz, &cz);
    c = y * cz;
    s = y * sz;
}

// ---------------------------------------------------------------------------
// Block (j = chunk, g = 32-channel group), 256 threads, 1 block/SM.
// cp.async staging (2 stages) -> GEMM (f32x2, k-split halves, separate P bufs)
// -> parallel scan 8x4 (folding the half-reduction into the read)
// -> publish g_E + flag -> wait producer flags -> carry -> single store.
// ---------------------------------------------------------------------------
__global__ __launch_bounds__(256, 1) void rtrl_kernel(
    const float* __restrict__ x,
    const float* __restrict__ B1,
    const float* __restrict__ B2,
    const float* __restrict__ lamda,
    const float* __restrict__ theta,
    float* __restrict__ out)
{
    extern __shared__ float sm[];
    float* as = sm + AS_OFF;
    float* bs = sm + BS_OFF;
    float* P0 = sm + P0_OFF;
    float* P1 = sm + P1_OFF;
    float* Es = sm + ES_OFF;
    int*   ep = (int*)(sm + EP_OFF);

    const int j   = blockIdx.x;        // chunk
    const int g   = blockIdx.y;        // channel group
    const int t0  = j * LCH;
    const int ch0 = g * 32;
    const int tid = threadIdx.x;
    const int ch  = tid & 31;
    const int sc  = tid >> 5;          // 0..7 (subchunk / t-slice)
    const int h   = ch0 + ch;

    // ---- async staging FIRST (critical path): stage s = k-strips {s, s+2} ----
    const float4* x4 = (const float4*)x;
#pragma unroll
    for (int s = 0; s < 2; s++) {
#pragma unroll
        for (int i = 0; i < 4; i++) {
            int idx = i * 256 + tid;
            int row = idx >> 5;                    // 0..31
            int qq  = idx & 31;
            int q   = ((qq >> 4) * 2 + s) * 16 + (qq & 15);
            cp16(&as[row * STRA + 4 * q], &x4[(t0 + row) * 64 + q]);
        }
#pragma unroll
        for (int i = 0; i < 8; i++) {
            int idx = i * 256 + tid;
            int row = idx >> 5;                    // 0..63
            int qq  = idx & 31;
            int q   = ((qq >> 4) * 2 + s) * 16 + (qq & 15);
            const float4* Bsrc = (row < 32)
                ? (const float4*)(B1 + (ch0 + row) * DD)
                : (const float4*)(B2 + (ch0 + row - 32) * DD);
            cp16(&bs[row * STRA + 4 * q], Bsrc + q);
        }
        CP_COMMIT();
    }

    // ---- per-channel coefficients + rotation powers (under copy latency) ----
    float cc, ss_, gam;
    coeffs(lamda, theta, h, cc, ss_, gam);
    float a4 = cc, b4 = ss_;
#pragma unroll
    for (int it = 0; it < 2; it++) { float na = a4*a4 - b4*b4, nb = 2.f*a4*b4; a4 = na; b4 = nb; }
    float a8 = a4, b8 = b4;     cmul(a4,  b4,  a8,  b8);     // R^8
    float a16 = a8, b16 = b8;   cmul(a8,  b8,  a16, b16);    // R^16
    float a32 = a16, b32 = b16; cmul(a16, b16, a32, b32);    // R^32

    // ---- GEMM: k-split halves, 4x4 strided micro-tile, f32x2 accumulators ----
    const int half = tid >> 7;         // 0/1 -> k quads [0,32) / [32,64)
    const int t7   = tid & 127;
    const int tsub = t7 >> 4;          // rows {tsub+8i}
    const int csub = t7 & 15;          // cols {csub+16i}
    const int kq0  = half * 32;

    unsigned long long acc[4][4];
#pragma unroll
    for (int i = 0; i < 4; i++)
#pragma unroll
        for (int jb = 0; jb < 4; jb++) acc[i][jb] = 0ull;

    CP_WAIT(1);
    __syncthreads();                   // stage A (strips 0,2) resident

#pragma unroll
    for (int ph = 0; ph < 2; ph++) {
        if (ph == 1) { CP_WAIT(0); __syncthreads(); }  // stage B resident
#pragma unroll
        for (int kq = ph * 16; kq < ph * 16 + 16; kq++) {
            int kf = (kq0 + kq) * 4;
            ulonglong2 av[4], bv[4];
#pragma unroll
            for (int i = 0; i < 4; i++)
                av[i] = *(const ulonglong2*)&as[(tsub + 8 * i) * STRA + kf];
#pragma unroll
            for (int i = 0; i < 4; i++)
                bv[i] = *(const ulonglong2*)&bs[(csub + 16 * i) * STRA + kf];
#pragma unroll
            for (int i = 0; i < 4; i++) {
#pragma unroll
                for (int jb = 0; jb < 4; jb++) {
                    FMA2(acc[i][jb], av[i].x, bv[jb].x);
                    FMA2(acc[i][jb], av[i].y, bv[jb].y);
                }
            }
        }
    }

    // ---- both halves store partials (no RMW, no extra sync) ----
    {
        float* Pm = half ? P1 : P0;
#pragma unroll
        for (int i = 0; i < 4; i++)
#pragma unroll
            for (int jb = 0; jb < 4; jb++)
                Pm[(tsub + 8 * i) * SS_STR + csub + 16 * jb] = f32x2_sum(acc[i][jb]);
    }
    __syncthreads();

    // ---- parallel in-chunk scan: 8 subchunks of 4 steps (fold half-add) ----
    float rl1[4], rl2[4];
    {
        float l1 = 0.f, l2 = 0.f;
#pragma unroll
        for (int i = 0; i < 4; i++) {
            int tt = 4 * sc + i;
            float b1 = P0[tt * SS_STR + ch]      + P1[tt * SS_STR + ch];
            float b2 = P0[tt * SS_STR + 32 + ch] + P1[tt * SS_STR + 32 + ch];
            float n1 = fmaf(cc, l1, fmaf(-ss_, l2, gam * b1));
            float n2 = fmaf(cc, l2, fmaf( ss_, l1, gam * b2));
            l1 = n1; l2 = n2;
            rl1[i] = l1; rl2[i] = l2;
        }
        Es[sc * 64 + ch]      = l1;
        Es[sc * 64 + 32 + ch] = l2;
    }
    __syncthreads();

    // compose subchunk carry and correct locals
    {
        float p1 = 0.f, p2 = 0.f;
#pragma unroll
        for (int u = 0; u < 7; u++) {
            if (u < sc) {
                float e1 = Es[u * 64 + ch];
                float e2 = Es[u * 64 + 32 + ch];
                float n1 = fmaf(a4, p1, fmaf(-b4, p2, e1));
                float n2 = fmaf(a4, p2, fmaf( b4, p1, e2));
                p1 = n1; p2 = n2;
            }
        }
#pragma unroll
        for (int i = 0; i < 4; i++) {
            float n1 = fmaf(cc, p1, -ss_ * p2);
            float n2 = fmaf(cc, p2,  ss_ * p1);
            p1 = n1; p2 = n2;
            rl1[i] += p1; rl2[i] += p2;
        }
    }

    // ---- publish chunk end state + padded flag (monotonic, replay-safe) ----
    if (sc == 7) {
        g_E[j * H2 + h]      = rl1[3];
        g_E[j * H2 + HH + h] = rl2[3];
        __threadfence();
    }
    __syncthreads();
    if (tid == 0) {
        int ticket = atomicAdd(&g_flag[j * FLAG_STRIDE], 1);
        *ep = ticket >> 3;             // 8 publishers per chunk
    }
    __syncthreads();

    // ---- wait only on producer chunks i < j (threads 0..j-1 poll, pure spin) ----
    if (j > 0) {
        int target = ((*ep) + 1) << 3;
        if (tid < j) {
            while (*((volatile int*)&g_flag[tid * FLAG_STRIDE]) < target) { }
            __threadfence();
        }
        __syncthreads();
    }

    // ---- cross-chunk carry ----
    float p1 = 0.f, p2 = 0.f;
#pragma unroll
    for (int i = 0; i < NCHUNK - 1; i++) {
        if (i < j) {
            float e1 = __ldcg(&g_E[i * H2 + h]);
            float e2 = __ldcg(&g_E[i * H2 + HH + h]);
            float n1 = fmaf(a32, p1, fmaf(-b32, p2, e1));
            float n2 = fmaf(a32, p2, fmaf( b32, p1, e2));
            p1 = n1; p2 = n2;
        }
    }
    // rotate carry to t-slice start: p *= R4^sc (binary exponent, <=3 cmuls)
    if (sc & 1) cmul(a4,  b4,  p1, p2);
    if (sc & 2) cmul(a8,  b8,  p1, p2);
    if (sc & 4) cmul(a16, b16, p1, p2);

    // ---- final single store of out ----
#pragma unroll
    for (int i = 0; i < 4; i++) {
        float n1 = fmaf(cc, p1, -ss_ * p2);
        float n2 = fmaf(cc, p2,  ss_ * p1);
        p1 = n1; p2 = n2;
        int tt = 4 * sc + i;
        out[(t0 + tt) * H2 + h]      = rl1[i] + p1;
        out[(t0 + tt) * H2 + HH + h] = rl2[i] + p2;
    }
}

// ---------------------------------------------------------------------------
extern "C" void kernel_launch(void* const* d_in, const int* in_sizes, int n_in,
                              void* d_out, int out_size)
{
    const float* x     = (const float*)d_in[0];
    const float* lamda = (const float*)d_in[1];
    const float* theta = (const float*)d_in[2];
    const float* B1    = (const float*)d_in[3];
    const float* B2    = (const float*)d_in[4];
    float* out = (float*)d_out;

    static bool attr_set = false;
    if (!attr_set) {
        cudaFuncSetAttribute(rtrl_kernel,
                             cudaFuncAttributeMaxDynamicSharedMemorySize,
                             SMEM_BYTES);
        attr_set = true;
    }

    dim3 grid(NCHUNK, HH / 32);        // (16, 8) = 128 blocks, all co-resident
    rtrl_kernel<<<grid, 256, SMEM_BYTES>>>(x, B1, B2, lamda, theta, out);
}

// round 11
// speedup vs baseline: 1.5363x; 1.5363x over previous
#include <cuda_runtime.h>
#include <math.h>
#include <stdint.h>

// Problem dims
#define TT   512
#define DD   256
#define HH   256
#define H2   512

#define NCHUNK 16
#define LCH    32

// smem layout (floats)
#define STRA 260                       // padded k-major row stride (16B-aligned rows)
#define AS_OFF 0                       // as[32][260]
#define BS_OFF (32 * STRA)             // bs[64][260]
#define P0_OFF (BS_OFF + 64 * STRA)    // P0[32][68] (k-half 0 partials)
#define P1_OFF (P0_OFF + 32 * 68)      // P1[32][68] (k-half 1 partials)
#define SS_STR 68
#define ES_OFF AS_OFF                  // Es[8][64] reuses as[] after GEMM
#define EP_OFF (P1_OFF + 32 * 68)      // epoch broadcast (1 int)
#define SMEM_FLOATS (EP_OFF + 1)
#define SMEM_BYTES (SMEM_FLOATS * 4)   // ~117 KB -> 1 block/SM

#define FLAG_STRIDE 32                 // 128 B between chunk flags

__device__ float g_E[NCHUNK * H2];     // per-chunk end states
__device__ int   g_flag[NCHUNK * FLAG_STRIDE];  // monotonic publish counters

#define FMA2(acc, a, b) \
    asm("fma.rn.f32x2 %0, %1, %2, %0;" : "+l"(acc) : "l"(a), "l"(b))

__device__ __forceinline__ float f32x2_sum(unsigned long long v) {
    float lo, hi;
    asm("mov.b64 {%0, %1}, %2;" : "=f"(lo), "=f"(hi) : "l"(v));
    return lo + hi;
}

__device__ __forceinline__ void cp16(float* smem_dst, const void* gsrc) {
    uint32_t sa = (uint32_t)__cvta_generic_to_shared(smem_dst);
    asm volatile("cp.async.cg.shared.global [%0], [%1], 16;" :: "r"(sa), "l"(gsrc));
}
#define CP_COMMIT() asm volatile("cp.async.commit_group;" ::: "memory")
#define CP_WAIT(n)  asm volatile("cp.async.wait_group %0;" :: "n"(n) : "memory")

__device__ __forceinline__ void cmul(float a, float b, float& p1, float& p2) {
    float n1 = a * p1 - b * p2;
    float n2 = fmaf(a, p2, b * p1);
    p1 = n1; p2 = n2;
}

__device__ __forceinline__ void coeffs(const float* __restrict__ lamda,
                                       const float* __restrict__ theta,
                                       int h, float& c, float& s, float& gam)
{
    float e = expf(lamda[h]);
    float y = expf(-e);
    float z = expf(theta[h]);
    gam = sqrtf(fmaxf(1.0f - y * y, 0.0f));
    float cz, sz;
    sincosf(z, &sz, &cz);
    c = y * cz;
    s = y * sz;
}

// ---------------------------------------------------------------------------
// Block (j = chunk, g = 32-channel group), 256 threads, 1 block/SM.
// cp.async staging (2 stages, issued FIRST) -> GEMM (f32x2, k-split halves,
// separate P buffers, no reduce pass) -> parallel scan 8x4 (half-add folded
// into the read) -> publish g_E + flag -> wait producer flags (nanosleep
// backoff) -> cross-chunk carry -> single store of out.
// ---------------------------------------------------------------------------
__global__ __launch_bounds__(256, 1) void rtrl_kernel(
    const float* __restrict__ x,
    const float* __restrict__ B1,
    const float* __restrict__ B2,
    const float* __restrict__ lamda,
    const float* __restrict__ theta,
    float* __restrict__ out)
{
    extern __shared__ float sm[];
    float* as = sm + AS_OFF;
    float* bs = sm + BS_OFF;
    float* P0 = sm + P0_OFF;
    float* P1 = sm + P1_OFF;
    float* Es = sm + ES_OFF;
    int*   ep = (int*)(sm + EP_OFF);

    const int j   = blockIdx.x;        // chunk
    const int g   = blockIdx.y;        // channel group
    const int t0  = j * LCH;
    const int ch0 = g * 32;
    const int tid = threadIdx.x;
    const int ch  = tid & 31;
    const int sc  = tid >> 5;          // 0..7 (subchunk / t-slice)
    const int h   = ch0 + ch;

    // ---- async staging FIRST (critical path): stage s = k-strips {s, s+2} ----
    const float4* x4 = (const float4*)x;
#pragma unroll
    for (int s = 0; s < 2; s++) {
#pragma unroll
        for (int i = 0; i < 4; i++) {
            int idx = i * 256 + tid;
            int row = idx >> 5;                    // 0..31
            int qq  = idx & 31;
            int q   = ((qq >> 4) * 2 + s) * 16 + (qq & 15);
            cp16(&as[row * STRA + 4 * q], &x4[(t0 + row) * 64 + q]);
        }
#pragma unroll
        for (int i = 0; i < 8; i++) {
            int idx = i * 256 + tid;
            int row = idx >> 5;                    // 0..63
            int qq  = idx & 31;
            int q   = ((qq >> 4) * 2 + s) * 16 + (qq & 15);
            const float4* Bsrc = (row < 32)
                ? (const float4*)(B1 + (ch0 + row) * DD)
                : (const float4*)(B2 + (ch0 + row - 32) * DD);
            cp16(&bs[row * STRA + 4 * q], Bsrc + q);
        }
        CP_COMMIT();
    }

    // ---- per-channel coefficients + rotation powers (under copy latency) ----
    float cc, ss_, gam;
    coeffs(lamda, theta, h, cc, ss_, gam);
    float a4 = cc, b4 = ss_;
#pragma unroll
    for (int it = 0; it < 2; it++) { float na = a4*a4 - b4*b4, nb = 2.f*a4*b4; a4 = na; b4 = nb; }
    float a8 = a4, b8 = b4;     cmul(a4,  b4,  a8,  b8);     // R^8
    float a16 = a8, b16 = b8;   cmul(a8,  b8,  a16, b16);    // R^16
    float a32 = a16, b32 = b16; cmul(a16, b16, a32, b32);    // R^32

    // ---- GEMM: k-split halves, 4x4 strided micro-tile, f32x2 accumulators ----
    const int half = tid >> 7;         // 0/1 -> k quads [0,32) / [32,64)
    const int t7   = tid & 127;
    const int tsub = t7 >> 4;          // rows {tsub+8i}
    const int csub = t7 & 15;          // cols {csub+16i}
    const int kq0  = half * 32;

    unsigned long long acc[4][4];
#pragma unroll
    for (int i = 0; i < 4; i++)
#pragma unroll
        for (int jb = 0; jb < 4; jb++) acc[i][jb] = 0ull;

    CP_WAIT(1);
    __syncthreads();                   // stage A (strips 0,2) resident

#pragma unroll
    for (int ph = 0; ph < 2; ph++) {
        if (ph == 1) { CP_WAIT(0); __syncthreads(); }  // stage B resident
#pragma unroll
        for (int kq = ph * 16; kq < ph * 16 + 16; kq++) {
            int kf = (kq0 + kq) * 4;
            ulonglong2 av[4], bv[4];
#pragma unroll
            for (int i = 0; i < 4; i++)
                av[i] = *(const ulonglong2*)&as[(tsub + 8 * i) * STRA + kf];
#pragma unroll
            for (int i = 0; i < 4; i++)
                bv[i] = *(const ulonglong2*)&bs[(csub + 16 * i) * STRA + kf];
#pragma unroll
            for (int i = 0; i < 4; i++) {
#pragma unroll
                for (int jb = 0; jb < 4; jb++) {
                    FMA2(acc[i][jb], av[i].x, bv[jb].x);
                    FMA2(acc[i][jb], av[i].y, bv[jb].y);
                }
            }
        }
    }

    // ---- both halves store partials (no RMW, no extra sync) ----
    {
        float* Pm = half ? P1 : P0;
#pragma unroll
        for (int i = 0; i < 4; i++)
#pragma unroll
            for (int jb = 0; jb < 4; jb++)
                Pm[(tsub + 8 * i) * SS_STR + csub + 16 * jb] = f32x2_sum(acc[i][jb]);
    }
    __syncthreads();

    // ---- parallel in-chunk scan: 8 subchunks of 4 steps (fold half-add) ----
    float rl1[4], rl2[4];
    {
        float l1 = 0.f, l2 = 0.f;
#pragma unroll
        for (int i = 0; i < 4; i++) {
            int tt = 4 * sc + i;
            float b1 = P0[tt * SS_STR + ch]      + P1[tt * SS_STR + ch];
            float b2 = P0[tt * SS_STR + 32 + ch] + P1[tt * SS_STR + 32 + ch];
            float n1 = fmaf(cc, l1, fmaf(-ss_, l2, gam * b1));
            float n2 = fmaf(cc, l2, fmaf( ss_, l1, gam * b2));
            l1 = n1; l2 = n2;
            rl1[i] = l1; rl2[i] = l2;
        }
        Es[sc * 64 + ch]      = l1;
        Es[sc * 64 + 32 + ch] = l2;
    }
    __syncthreads();

    // compose subchunk carry and correct locals
    {
        float p1 = 0.f, p2 = 0.f;
#pragma unroll
        for (int u = 0; u < 7; u++) {
            if (u < sc) {
                float e1 = Es[u * 64 + ch];
                float e2 = Es[u * 64 + 32 + ch];
                float n1 = fmaf(a4, p1, fmaf(-b4, p2, e1));
                float n2 = fmaf(a4, p2, fmaf( b4, p1, e2));
                p1 = n1; p2 = n2;
            }
        }
#pragma unroll
        for (int i = 0; i < 4; i++) {
            float n1 = fmaf(cc, p1, -ss_ * p2);
            float n2 = fmaf(cc, p2,  ss_ * p1);
            p1 = n1; p2 = n2;
            rl1[i] += p1; rl2[i] += p2;
        }
    }

    // ---- publish chunk end state + padded flag (monotonic, replay-safe) ----
    if (sc == 7) {
        g_E[j * H2 + h]      = rl1[3];
        g_E[j * H2 + HH + h] = rl2[3];
        __threadfence();
    }
    __syncthreads();
    if (tid == 0) {
        int ticket = atomicAdd(&g_flag[j * FLAG_STRIDE], 1);
        *ep = ticket >> 3;             // 8 publishers per chunk
    }
    __syncthreads();

    // ---- wait only on producer chunks i < j (nanosleep backoff) ----
    if (j > 0) {
        int target = ((*ep) + 1) << 3;
        if (tid < j) {
            while (*((volatile int*)&g_flag[tid * FLAG_STRIDE]) < target)
                __nanosleep(64);
            __threadfence();
        }
        __syncthreads();
    }

    // ---- cross-chunk carry ----
    float p1 = 0.f, p2 = 0.f;
#pragma unroll
    for (int i = 0; i < NCHUNK - 1; i++) {
        if (i < j) {
            float e1 = __ldcg(&g_E[i * H2 + h]);
            float e2 = __ldcg(&g_E[i * H2 + HH + h]);
            float n1 = fmaf(a32, p1, fmaf(-b32, p2, e1));
            float n2 = fmaf(a32, p2, fmaf( b32, p1, e2));
            p1 = n1; p2 = n2;
        }
    }
    // rotate carry to t-slice start: p *= R4^sc (binary exponent, <=3 cmuls)
    if (sc & 1) cmul(a4,  b4,  p1, p2);
    if (sc & 2) cmul(a8,  b8,  p1, p2);
    if (sc & 4) cmul(a16, b16, p1, p2);

    // ---- final single store of out ----
#pragma unroll
    for (int i = 0; i < 4; i++) {
        float n1 = fmaf(cc, p1, -ss_ * p2);
        float n2 = fmaf(cc, p2,  ss_ * p1);
        p1 = n1; p2 = n2;
        int tt = 4 * sc + i;
        out[(t0 + tt) * H2 + h]      = rl1[i] + p1;
        out[(t0 + tt) * H2 + HH + h] = rl2[i] + p2;
    }
}

// ---------------------------------------------------------------------------
extern "C" void kernel_launch(void* const* d_in, const int* in_sizes, int n_in,
                              void* d_out, int out_size)
{
    const float* x     = (const float*)d_in[0];
    const float* lamda = (const float*)d_in[1];
    const float* theta = (const float*)d_in[2];
    const float* B1    = (const float*)d_in[3];
    const float* B2    = (const float*)d_in[4];
    float* out = (float*)d_out;

    static bool attr_set = false;
    if (!attr_set) {
        cudaFuncSetAttribute(rtrl_kernel,
                             cudaFuncAttributeMaxDynamicSharedMemorySize,
                             SMEM_BYTES);
        attr_set = true;
    }

    dim3 grid(NCHUNK, HH / 32);        // (16, 8) = 128 blocks, all co-resident
    rtrl_kernel<<<grid, 256, SMEM_BYTES>>>(x, B1, B2, lamda, theta, out);
}